// round 11
// baseline (speedup 1.0000x reference)
#include <cuda_runtime.h>
#include <math.h>

// ChebyshevDescriptor — 8 threads per atom, single kernel.
// N=20000, K=24, out [N,52] = [rad_un17 | rad_w17 | ang_un9 | ang_w9].
//
// R10 delta vs R9: fixed misaligned STS.64 — lane staging stride was 35
// floats (140B, odd-lane bases 4-mod-8); now RSTR=36 (144B) and ABLK=296 so
// every float2 staging address is 8B-aligned. Logic otherwise identical:
// no pack kernel (direct gathers), shared column-reduction instead of
// butterfly shuffles, uniform weight-masked r=12 tail.

#define N_ATOMS 20000
#define KNBR    24
#define RAD_CUT 8.0f
#define ANG_CUT 6.5f
#define MIN_CUT 0.55f
#define BT      64
#define APB     8            // atoms per block
#define SSTR    25           // padded float4 stride for u-table
#define RSTR    36           // floats per lane-row (even -> 8B-aligned float2)
#define ABLK    (8 * RSTR + 8)   // 296 floats per atom block (even; bank shift)

__global__ __launch_bounds__(BT, 17)
void cheb_kernel(const float* __restrict__ pos,
                 const int* __restrict__ spec,
                 const int* __restrict__ nbr,
                 float* __restrict__ out) {
    __shared__ float4 s_u4[APB][SSTR];                  // 3.2 KB
    __shared__ __align__(8) float s_red[APB * ABLK];    // 9.5 KB

    const int t = threadIdx.x;
    const int s = t & 7;                  // subthread within octet
    const int a = t >> 3;                 // atom within block
    const int atom = blockIdx.x * APB + a;    // 2500 * 8 == 20000 exactly

    const float px = pos[3 * atom + 0];
    const float py = pos[3 * atom + 1];
    const float pz = pos[3 * atom + 2];

    float* myrow = s_red + a * ABLK + s * RSTR;   // 8B-aligned for every lane

    // ---------------- pass 1: gather own 3 neighbors + radial partials ----------------
    float ru[17], rw[17];
    #pragma unroll
    for (int q = 0; q < 17; q++) { ru[q] = 0.0f; rw[q] = 0.0f; }

    float4 myu[3];

    #pragma unroll
    for (int m = 0; m < 3; m++) {
        const int j = s + 8 * m;
        const int nj = nbr[atom * KNBR + j];
        const float dx = pos[3 * nj + 0] - px;
        const float dy = pos[3 * nj + 1] - py;
        const float dz = pos[3 * nj + 2] - pz;
        const float sj = spec[nj] ? 1.0f : -1.0f;    // TYPESPIN = [-1, 1]
        const float d2 = dx * dx + dy * dy + dz * dz;
        const float inv = rsqrtf(fmaxf(d2, 1e-18f));
        const float d = d2 * inv;

        const bool mr = (d <= RAD_CUT) && (d > MIN_CUT);
        const float fc = 0.5f * (__cosf(d * (3.14159265358979f / RAD_CUT)) + 1.0f);
        const float wr  = mr ? fc : 0.0f;
        const float wrs = wr * sj;
        const float x = mr ? (2.0f * (d - MIN_CUT) * (1.0f / (RAD_CUT - MIN_CUT)) - 1.0f)
                           : 0.0f;   // weight 0 when masked; x=0 keeps T bounded

        const bool ma = (d <= ANG_CUT) && (d > MIN_CUT);
        const float fca = 0.5f * (__cosf(d * (3.14159265358979f / ANG_CUT)) + 1.0f);
        const float wa = ma ? fca : 0.0f;

        const float4 u = make_float4(dx * inv, dy * inv, dz * inv, wa * sj);
        myu[m] = u;
        s_u4[a][j] = u;

        ru[0] += wr;        rw[0] += wrs;
        ru[1] += wr * x;    rw[1] += wrs * x;
        const float x2 = x + x;
        float Tmm = 1.0f, Tm = x;
        #pragma unroll
        for (int q = 2; q < 17; q++) {
            const float T = x2 * Tm - Tmm;
            ru[q] += wr * T;
            rw[q] += wrs * T;
            Tmm = Tm; Tm = T;
        }
    }

    // stage radial partials: 17 float2 (ru[q], rw[q]) per lane
    #pragma unroll
    for (int q = 0; q < 17; q++)
        *(float2*)(myrow + 2 * q) = make_float2(ru[q], rw[q]);

    __syncwarp();

    // radial column-reduce: lane s sums columns c = s + 8i over the 8 rows
    // storage col for output col c: c<17 -> 2c (ru) else 2(c-17)+1 (rw)
    float* o = out + (size_t)atom * 52;
    const float* ared = s_red + a * ABLK;
    #pragma unroll
    for (int i = 0; i < 5; i++) {
        const int c = s + 8 * i;
        if (c < 34) {
            const int sc = (c < 17) ? (2 * c) : (2 * (c - 17) + 1);
            float sum = 0.0f;
            #pragma unroll
            for (int r = 0; r < 8; r++) sum += ared[r * RSTR + sc];
            o[c] = sum;
        }
    }

    __syncwarp();   // radial reads done before angular staging overwrites

    // ---------------- pass 2: angular, rotation pairs ----------------
    float aU[9], aW[9];
    #pragma unroll
    for (int q = 0; q < 9; q++) { aU[q] = 0.0f; aW[q] = 0.0f; }

    const float4* srow = &s_u4[a][0];

    #pragma unroll 1
    for (int r = 1; r <= 11; r++) {
        const int k0 = s + r;
        #pragma unroll
        for (int m = 0; m < 3; m++) {
            int k = k0 + 8 * m;
            if (k >= KNBR) k -= KNBR;
            const float4 av = myu[m];
            const float4 b = srow[k];

            const float wsp = av.w * b.w;     // (wa_j sj)(wa_k sk)
            const float wp  = fabsf(wsp);     // wa_j wa_k
            const float ct = av.x * b.x + av.y * b.y + av.z * b.z;   // |ct|<=1+ulp

            aU[0] += wp;        aW[0] += wsp;
            aU[1] += wp * ct;   aW[1] += wsp * ct;
            const float c2 = ct + ct;
            float Tmm = 1.0f, Tm = ct;
            #pragma unroll
            for (int q = 2; q < 9; q++) {
                const float T = c2 * Tm - Tmm;
                aU[q] += wp * T;
                aW[q] += wsp * T;
                Tmm = Tm; Tm = T;
            }
        }
    }
    // r = 12 tail, uniform: m=0 always valid; m=1 valid only for s<4
    // (s>=4, m=1 duplicates the pair owned by lane s-4 -> weight-masked to 0)
    #pragma unroll
    for (int m = 0; m < 2; m++) {
        int k = s + 12 + 8 * m;
        if (k >= KNBR) k -= KNBR;
        const float4 av = myu[m];
        const float4 b = srow[k];
        const float msk = (m == 0 || s < 4) ? 1.0f : 0.0f;

        const float wsp = msk * av.w * b.w;
        const float wp  = fabsf(wsp);
        const float ct = av.x * b.x + av.y * b.y + av.z * b.z;

        aU[0] += wp;        aW[0] += wsp;
        aU[1] += wp * ct;   aW[1] += wsp * ct;
        const float c2 = ct + ct;
        float Tmm = 1.0f, Tm = ct;
        #pragma unroll
        for (int q = 2; q < 9; q++) {
            const float T = c2 * Tm - Tmm;
            aU[q] += wp * T;
            aW[q] += wsp * T;
            Tmm = Tm; Tm = T;
        }
    }

    // stage angular partials: 9 float2 per lane (reusing the scratch region)
    #pragma unroll
    for (int q = 0; q < 9; q++)
        *(float2*)(myrow + 2 * q) = make_float2(aU[q], aW[q]);

    __syncwarp();

    // angular column-reduce: 18 columns, lane s takes c = s + 8i
    // storage col: c<9 -> 2c (aU) else 2(c-9)+1 (aW); output col 34+c
    #pragma unroll
    for (int i = 0; i < 3; i++) {
        const int c = s + 8 * i;
        if (c < 18) {
            const int sc = (c < 9) ? (2 * c) : (2 * (c - 9) + 1);
            float sum = 0.0f;
            #pragma unroll
            for (int r = 0; r < 8; r++) sum += ared[r * RSTR + sc];
            o[34 + c] = sum;
        }
    }
}

extern "C" void kernel_launch(void* const* d_in, const int* in_sizes, int n_in,
                              void* d_out, int out_size) {
    const float* positions  = (const float*)d_in[0];
    const int* species_idx  = (const int*)d_in[1];
    const int* neighbor_idx = (const int*)d_in[2];
    float* out = (float*)d_out;

    cheb_kernel<<<N_ATOMS / APB, BT>>>(positions, species_idx, neighbor_idx, out);
}